// round 3
// baseline (speedup 1.0000x reference)
#include <cuda_runtime.h>
#include <math.h>

#define MAX_EDGES 100000
#define MAX_PART  256   // >= ceil(20000/256) = 79

__device__ float g_scores[MAX_EDGES];
__device__ float g_pmax[MAX_PART];
__device__ int   g_pidx[MAX_PART];
__device__ float g_psum[MAX_PART];
__device__ unsigned int g_ticket;   // zero-initialized; reset by last block each run

// ---------------------------------------------------------------------------
// Kernel 1: s[e] = dot(edge_emb[e,:256], W)
// One warp per FOUR edges: 8 independent LDG.128 per lane -> high MLP,
// shuffle-reduction + store amortized over 4 KB.
// ---------------------------------------------------------------------------
__global__ void __launch_bounds__(256) score_kernel(
        const float* __restrict__ emb,
        const float* __restrict__ W,
        float* __restrict__ s,
        int n_edges4) {          // multiple of 4
    int warp = (blockIdx.x * blockDim.x + threadIdx.x) >> 5;
    int lane = threadIdx.x & 31;
    int e0 = warp * 4;
    if (e0 >= n_edges4) return;

    const float4* w = reinterpret_cast<const float4*>(W);
    float4 w0 = __ldg(&w[lane * 2]);
    float4 w1 = __ldg(&w[lane * 2 + 1]);

    const float4* p0 = reinterpret_cast<const float4*>(emb + (size_t)e0 * 256);

    // 8 independent 16B loads (4 rows x 2 per lane)
    float4 a0 = p0[lane * 2];
    float4 a1 = p0[lane * 2 + 1];
    float4 b0 = p0[64 + lane * 2];
    float4 b1 = p0[64 + lane * 2 + 1];
    float4 c0 = p0[128 + lane * 2];
    float4 c1 = p0[128 + lane * 2 + 1];
    float4 d0 = p0[192 + lane * 2];
    float4 d1 = p0[192 + lane * 2 + 1];

    float accA = a0.x*w0.x + a0.y*w0.y + a0.z*w0.z + a0.w*w0.w
               + a1.x*w1.x + a1.y*w1.y + a1.z*w1.z + a1.w*w1.w;
    float accB = b0.x*w0.x + b0.y*w0.y + b0.z*w0.z + b0.w*w0.w
               + b1.x*w1.x + b1.y*w1.y + b1.z*w1.z + b1.w*w1.w;
    float accC = c0.x*w0.x + c0.y*w0.y + c0.z*w0.z + c0.w*w0.w
               + c1.x*w1.x + c1.y*w1.y + c1.z*w1.z + c1.w*w1.w;
    float accD = d0.x*w0.x + d0.y*w0.y + d0.z*w0.z + d0.w*w0.w
               + d1.x*w1.x + d1.y*w1.y + d1.z*w1.z + d1.w*w1.w;

    #pragma unroll
    for (int o = 16; o; o >>= 1) {
        accA += __shfl_xor_sync(0xFFFFFFFFu, accA, o);
        accB += __shfl_xor_sync(0xFFFFFFFFu, accB, o);
        accC += __shfl_xor_sync(0xFFFFFFFFu, accC, o);
        accD += __shfl_xor_sync(0xFFFFFFFFu, accD, o);
    }

    if (lane == 0) {
        float4 r = make_float4(accA, accB, accC, accD);
        *reinterpret_cast<float4*>(s + e0) = r;   // e0 % 4 == 0 -> 16B aligned
    }
}

// ---------------------------------------------------------------------------
// Kernel 2 (fused): per-path masked logits + per-block flash-softmax partials,
// then the LAST block (atomic ticket) combines partials and finishes:
//   p = argmax (first-occurrence), logprob = -log(sum exp(l - M)),
//   z[p] = ragged mean of winner's embedding rows.
// out: [0]=p, [1]=logprob, [2..257]=z[p]
// ---------------------------------------------------------------------------
__global__ void __launch_bounds__(256) paths_fused_kernel(
        const int* __restrict__ paths,
        const int* __restrict__ path_lens,
        const int* __restrict__ path_mask,
        const float* __restrict__ s,
        const float* __restrict__ b,
        const float* __restrict__ emb,
        int n_paths, int max_len, int n_blocks,
        float* __restrict__ out) {
    __shared__ float smax[256];
    __shared__ int   sidx[256];
    __shared__ float ssum[256];
    __shared__ int   s_is_last;

    int t = threadIdx.x;
    int i = blockIdx.x * 256 + t;

    // ---- per-thread logit ----
    float logit = -INFINITY;
    int   idx   = 0x7FFFFFFF;
    if (i < n_paths) {
        int len = path_lens[i] + 1;
        const int4* row = reinterpret_cast<const int4*>(paths + (size_t)i * max_len);
        int4 r0 = row[0], r1 = row[1], r2 = row[2], r3 = row[3];
        int e[16] = { r0.x, r0.y, r0.z, r0.w, r1.x, r1.y, r1.z, r1.w,
                      r2.x, r2.y, r2.z, r2.w, r3.x, r3.y, r3.z, r3.w };
        float sum = 0.0f;
        #pragma unroll
        for (int j = 0; j < 16; ++j)
            if (j < len) sum += s[e[j]];
        logit = sum / (float)len + b[0];
        if (path_mask[i] == 0) logit = -1e9f;
        idx = i;
    }

    // ---- block argmax (first-occurrence tiebreak) ----
    smax[t] = logit; sidx[t] = idx;
    __syncthreads();
    #pragma unroll
    for (int o = 128; o; o >>= 1) {
        if (t < o) {
            float v = smax[t + o]; int j = sidx[t + o];
            if (v > smax[t] || (v == smax[t] && j < sidx[t])) {
                smax[t] = v; sidx[t] = j;
            }
        }
        __syncthreads();
    }
    float bm = smax[0];

    // ---- block sumexp relative to block max ----
    float es = (i < n_paths) ? expf(logit - bm) : 0.0f;
    ssum[t] = es;
    __syncthreads();
    #pragma unroll
    for (int o = 128; o; o >>= 1) {
        if (t < o) ssum[t] += ssum[t + o];
        __syncthreads();
    }

    // ---- publish partials, grab ticket ----
    if (t == 0) {
        g_pmax[blockIdx.x] = bm;
        g_pidx[blockIdx.x] = sidx[0];
        g_psum[blockIdx.x] = ssum[0];
        __threadfence();                               // release partials
        unsigned rank = atomicAdd(&g_ticket, 1u);
        s_is_last = (rank == (unsigned)(n_blocks - 1));
    }
    __syncthreads();
    if (!s_is_last) return;

    // ================= LAST BLOCK: finalize =================
    __threadfence();   // acquire all blocks' partials

    float m = (t < n_blocks) ? g_pmax[t] : -INFINITY;
    int   j = (t < n_blocks) ? g_pidx[t] : 0x7FFFFFFF;
    smax[t] = m; sidx[t] = j;
    __syncthreads();
    #pragma unroll
    for (int o = 128; o; o >>= 1) {
        if (t < o) {
            float v = smax[t + o]; int k = sidx[t + o];
            if (v > smax[t] || (v == smax[t] && k < sidx[t])) {
                smax[t] = v; sidx[t] = k;
            }
        }
        __syncthreads();
    }
    float M = smax[0];
    int   p = sidx[0];
    __syncthreads();

    float e2 = (t < n_blocks) ? g_psum[t] * expf(g_pmax[t] - M) : 0.0f;
    ssum[t] = e2;
    __syncthreads();
    #pragma unroll
    for (int o = 128; o; o >>= 1) {
        if (t < o) ssum[t] += ssum[t + o];
        __syncthreads();
    }

    if (t == 0) {
        out[0] = (float)p;
        out[1] = -logf(ssum[0]);      // logits[p] == M
        g_ticket = 0;                 // reset for next graph replay
    }

    // z[p]: per-column ragged mean (256 columns, one per thread)
    {
        int len = path_lens[p] + 1;
        const int* row = paths + (size_t)p * max_len;
        float acc = 0.0f;
        for (int k = 0; k < len; ++k)
            acc += emb[(size_t)row[k] * 256 + t];
        out[2 + t] = acc / (float)len;
    }
}

// ---------------------------------------------------------------------------
// Launch
// Inputs: edge_emb f32[100000,256], paths i32[20000,16], path_lens i32[20000],
//         path_mask i32[20000], W f32[1,256], b f32[1], deterministic i32[1]
// ---------------------------------------------------------------------------
extern "C" void kernel_launch(void* const* d_in, const int* in_sizes, int n_in,
                              void* d_out, int out_size) {
    const float* edge_emb  = (const float*)d_in[0];
    const int*   paths     = (const int*)d_in[1];
    const int*   path_lens = (const int*)d_in[2];
    const int*   path_mask = (const int*)d_in[3];
    const float* W         = (const float*)d_in[4];
    const float* b         = (const float*)d_in[5];

    int hidden  = in_sizes[4];              // 256
    int n_edges = in_sizes[0] / hidden;     // 100000 (multiple of 4)
    int n_paths = in_sizes[2];              // 20000
    int max_len = in_sizes[1] / n_paths;    // 16

    float* out = (float*)d_out;

    float* scores; cudaGetSymbolAddress((void**)&scores, g_scores);

    // K1: 4 edges per warp, 8 warps per block -> 32 edges per block
    {
        int n_edges4 = n_edges & ~3;
        int edges_per_block = 32;
        int blocks = (n_edges4 + edges_per_block - 1) / edges_per_block;
        score_kernel<<<blocks, 256>>>(edge_emb, W, scores, n_edges4);
        // tail (n_edges not multiple of 4) doesn't occur here; n_edges=100000
    }

    // K2 fused: partials + last-block finalize
    int nb2 = (n_paths + 255) / 256;
    paths_fused_kernel<<<nb2, 256>>>(paths, path_lens, path_mask,
                                     scores, b, edge_emb,
                                     n_paths, max_len, nb2, out);
}

// round 4
// speedup vs baseline: 1.8361x; 1.8361x over previous
#include <cuda_runtime.h>
#include <math.h>

#define MAX_EDGES 100000
#define MAX_PART  256   // >= ceil(20000/128) = 157

__device__ float g_scores[MAX_EDGES];
__device__ float g_pmax[MAX_PART];
__device__ int   g_pidx[MAX_PART];
__device__ float g_psum[MAX_PART];

// ---------------------------------------------------------------------------
// Kernel 1: s[e] = dot(edge_emb[e,:256], W)   [known-good R2 version]
// One warp per TWO edges: 4 independent LDG.128 per lane (MLP_p1 at the
// sweet spot below the L1tex-queue contention threshold).
// ---------------------------------------------------------------------------
__global__ void __launch_bounds__(256) score_kernel(
        const float* __restrict__ emb,
        const float* __restrict__ W,
        float* __restrict__ s,
        int n_edges) {
    int warp = (blockIdx.x * blockDim.x + threadIdx.x) >> 5;
    int lane = threadIdx.x & 31;
    int e0 = warp * 2;
    if (e0 >= n_edges) return;

    const float4* w = reinterpret_cast<const float4*>(W);
    float4 w0 = __ldg(&w[lane * 2]);
    float4 w1 = __ldg(&w[lane * 2 + 1]);

    const float4* p0 = reinterpret_cast<const float4*>(emb + (size_t)e0 * 256);
    const float4* p1 = p0 + 64;

    float4 a0 = p0[lane * 2];
    float4 a1 = p0[lane * 2 + 1];
    float4 b0 = p1[lane * 2];
    float4 b1 = p1[lane * 2 + 1];

    float accA = a0.x*w0.x + a0.y*w0.y + a0.z*w0.z + a0.w*w0.w
               + a1.x*w1.x + a1.y*w1.y + a1.z*w1.z + a1.w*w1.w;
    float accB = b0.x*w0.x + b0.y*w0.y + b0.z*w0.z + b0.w*w0.w
               + b1.x*w1.x + b1.y*w1.y + b1.z*w1.z + b1.w*w1.w;

    #pragma unroll
    for (int o = 16; o; o >>= 1) {
        accA += __shfl_xor_sync(0xFFFFFFFFu, accA, o);
        accB += __shfl_xor_sync(0xFFFFFFFFu, accB, o);
    }

    if (lane == 0) {
        s[e0] = accA;
        if (e0 + 1 < n_edges) s[e0 + 1] = accB;
    }
}

// ---------------------------------------------------------------------------
// Kernel 2: per-path masked logit + per-block flash-softmax partials.
// 128-thread blocks -> 157 blocks -> covers all 148 SMs (R2 used 79 blocks
// and left half the chip idle on a latency-bound gather).
// ---------------------------------------------------------------------------
__global__ void __launch_bounds__(128) logits_partial_kernel(
        const int* __restrict__ paths,
        const int* __restrict__ path_lens,
        const int* __restrict__ path_mask,
        const float* __restrict__ s,
        const float* __restrict__ b,
        int n_paths, int max_len) {
    __shared__ float smax[128];
    __shared__ int   sidx[128];
    __shared__ float ssum[128];

    int t = threadIdx.x;
    int i = blockIdx.x * 128 + t;

    float logit = -INFINITY;
    int   idx   = 0x7FFFFFFF;
    if (i < n_paths) {
        int len = path_lens[i] + 1;
        const int4* row = reinterpret_cast<const int4*>(paths + (size_t)i * max_len);
        int4 r0 = row[0], r1 = row[1], r2 = row[2], r3 = row[3];
        int e[16] = { r0.x, r0.y, r0.z, r0.w, r1.x, r1.y, r1.z, r1.w,
                      r2.x, r2.y, r2.z, r2.w, r3.x, r3.y, r3.z, r3.w };
        float sum = 0.0f;
        #pragma unroll
        for (int j = 0; j < 16; ++j)
            if (j < len) sum += s[e[j]];
        logit = sum / (float)len + b[0];
        if (path_mask[i] == 0) logit = -1e9f;
        idx = i;
    }

    smax[t] = logit; sidx[t] = idx;
    __syncthreads();
    #pragma unroll
    for (int o = 64; o; o >>= 1) {
        if (t < o) {
            float v = smax[t + o]; int j = sidx[t + o];
            if (v > smax[t] || (v == smax[t] && j < sidx[t])) {
                smax[t] = v; sidx[t] = j;
            }
        }
        __syncthreads();
    }
    float bm = smax[0];

    float es = (i < n_paths) ? expf(logit - bm) : 0.0f;
    ssum[t] = es;
    __syncthreads();
    #pragma unroll
    for (int o = 64; o; o >>= 1) {
        if (t < o) ssum[t] += ssum[t + o];
        __syncthreads();
    }

    if (t == 0) {
        g_pmax[blockIdx.x] = bm;
        g_pidx[blockIdx.x] = sidx[0];
        g_psum[blockIdx.x] = ssum[0];
    }
}

// ---------------------------------------------------------------------------
// Kernel 3 (single block, 256 threads): combine <=256 partials, then z[p].
// logits[p] == global max M  =>  logprob = -log(sum exp(l - M)).
// out: [0]=p, [1]=logprob, [2..257]=z[p]
// ---------------------------------------------------------------------------
__global__ void __launch_bounds__(256) finalize_kernel(
        int n_part,
        const float* __restrict__ emb,
        const int* __restrict__ paths,
        const int* __restrict__ path_lens,
        int max_len,
        float* __restrict__ out) {
    __shared__ float smax[256];
    __shared__ int   sidx[256];
    __shared__ float ssum[256];
    __shared__ float sM;
    __shared__ int   sp;

    int t = threadIdx.x;
    float m = (t < n_part) ? g_pmax[t] : -INFINITY;
    int   j = (t < n_part) ? g_pidx[t] : 0x7FFFFFFF;

    smax[t] = m; sidx[t] = j;
    __syncthreads();
    #pragma unroll
    for (int o = 128; o; o >>= 1) {
        if (t < o) {
            float v = smax[t + o]; int k = sidx[t + o];
            if (v > smax[t] || (v == smax[t] && k < sidx[t])) {
                smax[t] = v; sidx[t] = k;
            }
        }
        __syncthreads();
    }
    if (t == 0) { sM = smax[0]; sp = sidx[0]; }
    __syncthreads();
    float M = sM;
    int p = sp;

    float es = (t < n_part) ? g_psum[t] * expf(g_pmax[t] - M) : 0.0f;
    ssum[t] = es;
    __syncthreads();
    #pragma unroll
    for (int o = 128; o; o >>= 1) {
        if (t < o) ssum[t] += ssum[t + o];
        __syncthreads();
    }

    if (t == 0) {
        out[0] = (float)p;
        out[1] = -logf(ssum[0]);   // logits[p] - M == 0
    }

    // z[p]: per-column ragged mean (256 columns, one per thread)
    {
        int len = path_lens[p] + 1;
        const int* row = paths + (size_t)p * max_len;
        float acc = 0.0f;
        for (int k = 0; k < len; ++k)
            acc += emb[(size_t)row[k] * 256 + t];
        out[2 + t] = acc / (float)len;
    }
}

// ---------------------------------------------------------------------------
// Launch
// Inputs: edge_emb f32[100000,256], paths i32[20000,16], path_lens i32[20000],
//         path_mask i32[20000], W f32[1,256], b f32[1], deterministic i32[1]
// ---------------------------------------------------------------------------
extern "C" void kernel_launch(void* const* d_in, const int* in_sizes, int n_in,
                              void* d_out, int out_size) {
    const float* edge_emb  = (const float*)d_in[0];
    const int*   paths     = (const int*)d_in[1];
    const int*   path_lens = (const int*)d_in[2];
    const int*   path_mask = (const int*)d_in[3];
    const float* W         = (const float*)d_in[4];
    const float* b         = (const float*)d_in[5];

    int hidden  = in_sizes[4];              // 256
    int n_edges = in_sizes[0] / hidden;     // 100000
    int n_paths = in_sizes[2];              // 20000
    int max_len = in_sizes[1] / n_paths;    // 16

    float* out = (float*)d_out;

    float* scores; cudaGetSymbolAddress((void**)&scores, g_scores);

    // K1: 2 edges per warp, 8 warps per block (known-good R2 config)
    {
        int edges_per_block = 16;
        int blocks = (n_edges + edges_per_block - 1) / edges_per_block;
        score_kernel<<<blocks, 256>>>(edge_emb, W, scores, n_edges);
    }

    // K2: one thread per path, 128-thread blocks -> 157 blocks (all SMs)
    int nb2 = (n_paths + 127) / 128;
    logits_partial_kernel<<<nb2, 128>>>(paths, path_lens, path_mask,
                                        scores, b, n_paths, max_len);

    // K3: combine partials + winner embedding mean
    finalize_kernel<<<1, 256>>>(nb2, edge_emb, paths, path_lens, max_len, out);
}

// round 5
// speedup vs baseline: 1.8595x; 1.0128x over previous
#include <cuda_runtime.h>
#include <math.h>

#define MAX_EDGES 100000
#define MAX_PART  256

__device__ float g_scores[MAX_EDGES];
__device__ float g_pmax[MAX_PART];
__device__ int   g_pidx[MAX_PART];
__device__ float g_psum[MAX_PART];
__device__ unsigned int g_ticket;   // zero-init; reset by last block each run

// ---------------------------------------------------------------------------
// Kernel 1: s[e] = dot(edge_emb[e,:256], W)
// Persistent grid-stride: each warp processes tiles of 2 edges, prefetching
// the next tile's 4x LDG.128 before reducing the current one, so loads stay
// in flight through the shuffle tail. __ldcs = streaming (don't pollute L2).
// ---------------------------------------------------------------------------
__global__ void __launch_bounds__(256) score_kernel(
        const float* __restrict__ emb,
        const float* __restrict__ W,
        float* __restrict__ s,
        int n_edges, int n_tiles, int total_warps) {
    int gw   = (blockIdx.x * blockDim.x + threadIdx.x) >> 5;
    int lane = threadIdx.x & 31;
    if (gw >= n_tiles) return;

    const float4* w = reinterpret_cast<const float4*>(W);
    float4 w0 = __ldg(&w[lane * 2]);
    float4 w1 = __ldg(&w[lane * 2 + 1]);

    int tile = gw;
    const float4* base = reinterpret_cast<const float4*>(emb);

    // prime: load tile's 2 rows (4 independent 16B loads per lane)
    const float4* p = base + (size_t)tile * 128;
    float4 a0 = __ldcs(&p[lane * 2]);
    float4 a1 = __ldcs(&p[lane * 2 + 1]);
    float4 b0 = __ldcs(&p[64 + lane * 2]);
    float4 b1 = __ldcs(&p[64 + lane * 2 + 1]);

    for (;;) {
        int next = tile + total_warps;
        bool have_next = next < n_tiles;

        float4 c0, c1, d0, d1;
        if (have_next) {           // prefetch next tile before reducing this one
            const float4* q = base + (size_t)next * 128;
            c0 = __ldcs(&q[lane * 2]);
            c1 = __ldcs(&q[lane * 2 + 1]);
            d0 = __ldcs(&q[64 + lane * 2]);
            d1 = __ldcs(&q[64 + lane * 2 + 1]);
        }

        float accA = a0.x*w0.x + a0.y*w0.y + a0.z*w0.z + a0.w*w0.w
                   + a1.x*w1.x + a1.y*w1.y + a1.z*w1.z + a1.w*w1.w;
        float accB = b0.x*w0.x + b0.y*w0.y + b0.z*w0.z + b0.w*w0.w
                   + b1.x*w1.x + b1.y*w1.y + b1.z*w1.z + b1.w*w1.w;

        #pragma unroll
        for (int o = 16; o; o >>= 1) {
            accA += __shfl_xor_sync(0xFFFFFFFFu, accA, o);
            accB += __shfl_xor_sync(0xFFFFFFFFu, accB, o);
        }

        if (lane == 0) {
            int e0 = tile * 2;
            s[e0] = accA;
            if (e0 + 1 < n_edges) s[e0 + 1] = accB;
        }

        if (!have_next) break;
        a0 = c0; a1 = c1; b0 = d0; b1 = d1;
        tile = next;
    }
}

// ---------------------------------------------------------------------------
// Kernel 2 (fused): per-path masked logits + per-block flash-softmax
// partials; the LAST block (atomic ticket) combines partials, computes
// p / logprob / z[p], and resets the ticket for the next graph replay.
// out: [0]=p, [1]=logprob, [2..257]=z[p]
// ---------------------------------------------------------------------------
__global__ void __launch_bounds__(256) paths_fused_kernel(
        const int* __restrict__ paths,
        const int* __restrict__ path_lens,
        const int* __restrict__ path_mask,
        const float* __restrict__ s,
        const float* __restrict__ b,
        const float* __restrict__ emb,
        int n_paths, int max_len, int n_blocks,
        float* __restrict__ out) {
    __shared__ float smax[256];
    __shared__ int   sidx[256];
    __shared__ float ssum[256];
    __shared__ int   s_is_last;

    int t = threadIdx.x;
    int i = blockIdx.x * 256 + t;

    float logit = -INFINITY;
    int   idx   = 0x7FFFFFFF;
    if (i < n_paths) {
        int len = path_lens[i] + 1;
        const int4* row = reinterpret_cast<const int4*>(paths + (size_t)i * max_len);
        int4 r0 = row[0], r1 = row[1], r2 = row[2], r3 = row[3];
        int e[16] = { r0.x, r0.y, r0.z, r0.w, r1.x, r1.y, r1.z, r1.w,
                      r2.x, r2.y, r2.z, r2.w, r3.x, r3.y, r3.z, r3.w };
        float sum = 0.0f;
        #pragma unroll
        for (int j = 0; j < 16; ++j)
            if (j < len) sum += s[e[j]];
        logit = sum / (float)len + b[0];
        if (path_mask[i] == 0) logit = -1e9f;
        idx = i;
    }

    // block argmax (first-occurrence tiebreak)
    smax[t] = logit; sidx[t] = idx;
    __syncthreads();
    #pragma unroll
    for (int o = 128; o; o >>= 1) {
        if (t < o) {
            float v = smax[t + o]; int j = sidx[t + o];
            if (v > smax[t] || (v == smax[t] && j < sidx[t])) {
                smax[t] = v; sidx[t] = j;
            }
        }
        __syncthreads();
    }
    float bm = smax[0];

    // block sumexp vs block max
    float es = (i < n_paths) ? expf(logit - bm) : 0.0f;
    ssum[t] = es;
    __syncthreads();
    #pragma unroll
    for (int o = 128; o; o >>= 1) {
        if (t < o) ssum[t] += ssum[t + o];
        __syncthreads();
    }

    // publish partials, draw ticket
    if (t == 0) {
        g_pmax[blockIdx.x] = bm;
        g_pidx[blockIdx.x] = sidx[0];
        g_psum[blockIdx.x] = ssum[0];
        __threadfence();                       // release partials
        unsigned rank = atomicAdd(&g_ticket, 1u);
        s_is_last = (rank == (unsigned)(n_blocks - 1));
    }
    __syncthreads();
    if (!s_is_last) return;

    // ===== last block: finalize =====
    __threadfence();                           // acquire all partials

    float m = (t < n_blocks) ? g_pmax[t] : -INFINITY;
    int   j = (t < n_blocks) ? g_pidx[t] : 0x7FFFFFFF;
    smax[t] = m; sidx[t] = j;
    __syncthreads();
    #pragma unroll
    for (int o = 128; o; o >>= 1) {
        if (t < o) {
            float v = smax[t + o]; int k = sidx[t + o];
            if (v > smax[t] || (v == smax[t] && k < sidx[t])) {
                smax[t] = v; sidx[t] = k;
            }
        }
        __syncthreads();
    }
    float M = smax[0];
    int   p = sidx[0];
    __syncthreads();

    float e2 = (t < n_blocks) ? g_psum[t] * expf(g_pmax[t] - M) : 0.0f;
    ssum[t] = e2;
    __syncthreads();
    #pragma unroll
    for (int o = 128; o; o >>= 1) {
        if (t < o) ssum[t] += ssum[t + o];
        __syncthreads();
    }

    if (t == 0) {
        out[0] = (float)p;
        out[1] = -logf(ssum[0]);   // logits[p] == M
        g_ticket = 0;              // reset for next replay
    }

    // z[p]: per-column ragged mean (256 columns, one per thread)
    {
        int len = path_lens[p] + 1;
        const int* row = paths + (size_t)p * max_len;
        float acc = 0.0f;
        for (int k = 0; k < len; ++k)
            acc += emb[(size_t)row[k] * 256 + t];
        out[2 + t] = acc / (float)len;
    }
}

// ---------------------------------------------------------------------------
// Launch
// Inputs: edge_emb f32[100000,256], paths i32[20000,16], path_lens i32[20000],
//         path_mask i32[20000], W f32[1,256], b f32[1], deterministic i32[1]
// ---------------------------------------------------------------------------
extern "C" void kernel_launch(void* const* d_in, const int* in_sizes, int n_in,
                              void* d_out, int out_size) {
    const float* edge_emb  = (const float*)d_in[0];
    const int*   paths     = (const int*)d_in[1];
    const int*   path_lens = (const int*)d_in[2];
    const int*   path_mask = (const int*)d_in[3];
    const float* W         = (const float*)d_in[4];
    const float* b         = (const float*)d_in[5];

    int hidden  = in_sizes[4];              // 256
    int n_edges = in_sizes[0] / hidden;     // 100000
    int n_paths = in_sizes[2];              // 20000
    int max_len = in_sizes[1] / n_paths;    // 16

    float* out = (float*)d_out;

    float* scores; cudaGetSymbolAddress((void**)&scores, g_scores);

    // K1: persistent grid-stride, 6 blocks per SM (148 SMs)
    {
        int n_tiles = (n_edges + 1) / 2;    // 2 edges per tile
        int blocks = 148 * 6;               // 888 blocks -> 7104 warps
        int total_warps = blocks * 8;
        score_kernel<<<blocks, 256>>>(edge_emb, W, scores,
                                      n_edges, n_tiles, total_warps);
    }

    // K2 fused: partials + last-block finalize (single launch)
    int nb2 = (n_paths + 255) / 256;        // 79
    paths_fused_kernel<<<nb2, 256>>>(paths, path_lens, path_mask,
                                     scores, b, edge_emb,
                                     n_paths, max_len, nb2, out);
}